// round 1
// baseline (speedup 1.0000x reference)
#include <cuda_runtime.h>
#include <math.h>

#define B 16
#define C 3
#define H 512
#define W 512
#define HW (H*W)
#define CHW (C*H*W)
#define KPOOL 15
#define KHALF 7
#define EPSV 1e-8f

// scalar accumulators: S1 (l1), S2 (win l1), S3 (color)
__device__ double g_acc[3];
// horizontal sliding-sum of detector map, [B,H,W]
__device__ float g_hsum[B*H*W];

__device__ __forceinline__ float fsig(float x) {
    return 1.0f / (1.0f + __expf(-x));
}

// One block per image row: compute detector map m in shared, horizontal sum of 15.
__global__ void k_hsum(const float* __restrict__ src) {
    int row = blockIdx.x;            // 0 .. B*H-1
    int b = row >> 9;
    int y = row & (H - 1);
    int x = threadIdx.x;             // 512 threads

    // Zero accumulators once per launch (any K1 block; K2 runs strictly after K1).
    if (row == 0 && x < 3) g_acc[x] = 0.0;

    __shared__ float m[W];
    const float* s = src + (size_t)b * CHW + (size_t)y * W;
    float s0 = s[x];
    float s1 = s[x + HW];
    float s2 = s[x + 2 * HW];
    float lum = 0.299f * s0 + 0.587f * s1 + 0.114f * s2;
    float mx = fmaxf(s0, fmaxf(s1, s2));
    float mn = fminf(s0, fminf(s1, s2));
    // src rescaled to [0,1]: brightness = 0.5*lum + 0.5 ; saturation = 0.5*(mx-mn)
    float bm = fsig(10.0f * lum - 3.0f);            // sigmoid(20*(bright-0.65))
    float sm = fsig(3.0f - 10.0f * (mx - mn));      // sigmoid(20*(0.15-sat))
    m[x] = bm * sm;
    __syncthreads();

    float sum = 0.0f;
#pragma unroll
    for (int d = -KHALF; d <= KHALF; ++d) {
        int xx = x + d;
        if (xx >= 0 && xx < W) sum += m[xx];
    }
    g_hsum[(size_t)row * W + x] = sum;
}

#define TX 32
#define TY 32
#define NWARPS 8

// Tile kernel: vertical pooling from g_hsum + all per-pixel loss math + reduction.
__global__ void k_main(const float* __restrict__ pred,
                       const float* __restrict__ tgt,
                       const float* __restrict__ src) {
    int tx = threadIdx.x;            // 0..31
    int ty = threadIdx.y;            // 0..7
    int b  = blockIdx.z;
    int x0 = blockIdx.x * TX;
    int y0 = blockIdx.y * TY;
    int x  = x0 + tx;

    __shared__ float hs[TY + KPOOL - 1][TX];   // 46 x 32

    // Load 46 hsum rows with vertical halo (zeros outside image).
    for (int r = ty; r < TY + KPOOL - 1; r += NWARPS) {
        int yg = y0 + r - KHALF;
        hs[r][tx] = (yg >= 0 && yg < H)
                      ? g_hsum[((size_t)b * H + yg) * W + x]
                      : 0.0f;
    }
    __syncthreads();

    float a1 = 0.0f, a2 = 0.0f, a3 = 0.0f;
    const size_t base = (size_t)b * CHW;

#pragma unroll
    for (int i = 0; i < TY / NWARPS; ++i) {
        int yl = ty * (TY / NWARPS) + i;     // 0..31
        int y  = y0 + yl;

        float vs = 0.0f;
#pragma unroll
        for (int d = 0; d < KPOOL; ++d) vs += hs[yl + d][tx];
        float wm = vs * (1.0f / 225.0f);      // window_mask

        size_t idx = base + (size_t)y * W + x;
        float p0 = pred[idx], p1 = pred[idx + HW], p2 = pred[idx + 2 * HW];
        float t0 = tgt[idx],  t1 = tgt[idx + HW],  t2 = tgt[idx + 2 * HW];
        float q0 = src[idx],  q1 = src[idx + HW],  q2 = src[idx + 2 * HW];

        float d0 = p0 - t0, d1 = p1 - t1, d2 = p2 - t2;
        float al1 = fabsf(d0) + fabsf(d1) + fabsf(d2);
        a1 += al1;
        a2 += al1 * (1.0f + 4.0f * wm);

        float st0 = t0 - q0, st1 = t1 - q1, st2 = t2 - q2;
        float sp0 = p0 - q0, sp1 = p1 - q1, sp2 = p2 - q2;
        float stm = sqrtf(st0 * st0 + st1 * st1 + st2 * st2);
        float spm = sqrtf(sp0 * sp0 + sp1 * sp1 + sp2 * sp2);
        float dot = st0 * sp0 + st1 * sp1 + st2 * sp2;
        float align = dot / (fmaxf(stm, EPSV) * fmaxf(spm, EPSV));
        float magl  = fabsf(spm / (stm + EPSV) - 1.0f);
        a3 += wm * (1.0f - align + 0.5f * magl);
    }

    // Warp reduce the three partials.
#pragma unroll
    for (int o = 16; o > 0; o >>= 1) {
        a1 += __shfl_down_sync(0xffffffffu, a1, o);
        a2 += __shfl_down_sync(0xffffffffu, a2, o);
        a3 += __shfl_down_sync(0xffffffffu, a3, o);
    }
    __shared__ float red[NWARPS][3];
    if (tx == 0) { red[ty][0] = a1; red[ty][1] = a2; red[ty][2] = a3; }
    __syncthreads();
    if (ty == 0 && tx == 0) {
        float r1 = 0.0f, r2 = 0.0f, r3 = 0.0f;
#pragma unroll
        for (int w = 0; w < NWARPS; ++w) { r1 += red[w][0]; r2 += red[w][1]; r3 += red[w][2]; }
        atomicAdd(&g_acc[0], (double)r1);
        atomicAdd(&g_acc[1], (double)r2);
        atomicAdd(&g_acc[2], (double)r3);
    }
}

__global__ void k_final(float* __restrict__ out) {
    const double N_ALL = (double)B * C * H * W;     // 12,582,912
    const double N_PIX = (double)B * H * W;         // 4,194,304
    double total = g_acc[0] / N_ALL            // LAMBDA_L1 * l1
                 + 3.0 * g_acc[1] / N_ALL      // LAMBDA_WIN_L1 * win_l1
                 + 2.0 * g_acc[2] / N_PIX;     // LAMBDA_WIN_COLOR * TRANSFORM_WEIGHT * color
    out[0] = (float)total;
}

extern "C" void kernel_launch(void* const* d_in, const int* in_sizes, int n_in,
                              void* d_out, int out_size) {
    const float* pred = (const float*)d_in[0];
    const float* tgt  = (const float*)d_in[1];
    const float* src  = (const float*)d_in[2];
    float* out = (float*)d_out;

    k_hsum<<<B * H, W>>>(src);
    dim3 grid(W / TX, H / TY, B);
    dim3 blk(TX, NWARPS);
    k_main<<<grid, blk>>>(pred, tgt, src);
    k_final<<<1, 1>>>(out);
}

// round 2
// speedup vs baseline: 1.3252x; 1.3252x over previous
#include <cuda_runtime.h>
#include <math.h>

#define B 16
#define C 3
#define H 512
#define W 512
#define HW (H*W)
#define CHW (C*H*W)
#define KPOOL 15
#define KHALF 7
#define EPSV 1e-8f

// scalar accumulators: S1 (l1), S2 (win l1), S3 (color)
__device__ double g_acc[3];
// horizontal sliding-sum of detector map, [B,H,W]
__device__ float g_hsum[B*H*W];

__device__ __forceinline__ float fsig(float x) {
    return 1.0f / (1.0f + __expf(-x));
}

// One block per image row (128 threads, 4 px/thread).
// Detector map -> padded smem -> 15-tap horizontal sum.
__global__ __launch_bounds__(128) void k_hsum(const float* __restrict__ src) {
    int row = blockIdx.x;            // 0 .. B*H-1
    int b = row >> 9;
    int y = row & (H - 1);
    int tid = threadIdx.x;           // 0..127

    if (row == 0 && tid < 3) g_acc[tid] = 0.0;

    // layout: m[1..7]=0 (left pad), m[8..519]=data, m[520..526]=0 (right pad)
    // pixel x's 15-tap window = m[x+1 .. x+15]
    __shared__ float m[528];

    const float* s = src + (size_t)b * CHW + (size_t)y * W;
    int x4 = tid * 4;
    float4 cr = *(const float4*)(s + x4);
    float4 cg = *(const float4*)(s + HW + x4);
    float4 cb = *(const float4*)(s + 2 * HW + x4);

    float rr[4] = {cr.x, cr.y, cr.z, cr.w};
    float gg[4] = {cg.x, cg.y, cg.z, cg.w};
    float bb[4] = {cb.x, cb.y, cb.z, cb.w};
    float mv[4];
#pragma unroll
    for (int i = 0; i < 4; ++i) {
        float lum = 0.299f * rr[i] + 0.587f * gg[i] + 0.114f * bb[i];
        float mx = fmaxf(rr[i], fmaxf(gg[i], bb[i]));
        float mn = fminf(rr[i], fminf(gg[i], bb[i]));
        // src rescaled to [0,1]: brightness = 0.5*lum+0.5 ; saturation = 0.5*(mx-mn)
        mv[i] = fsig(10.0f * lum - 3.0f) * fsig(3.0f - 10.0f * (mx - mn));
    }
    *(float4*)&m[8 + x4] = make_float4(mv[0], mv[1], mv[2], mv[3]);   // 16B aligned
    if (tid < 7) { m[1 + tid] = 0.0f; m[520 + tid] = 0.0f; }
    __syncthreads();

    // Strided pixel mapping: conflict-free stride-1 LDS taps, coalesced STG.
    float* out = g_hsum + (size_t)row * W;
#pragma unroll
    for (int j = 0; j < 4; ++j) {
        int x = tid + 128 * j;
        float sum = 0.0f;
#pragma unroll
        for (int d = 0; d < KPOOL; ++d) sum += m[x + 1 + d];
        out[x] = sum;
    }
}

#define TXV 128      // tile width in pixels
#define TY 32        // tile height
#define NW 8         // warps per block

// Tile kernel: vertical pooling from g_hsum + per-pixel loss math + reduction.
// Each thread owns a 4x4 patch: x = x0+4*tx..+3 (float4), rows y0+4*ty..+3.
__global__ __launch_bounds__(256) void k_main(const float* __restrict__ pred,
                                              const float* __restrict__ tgt,
                                              const float* __restrict__ src) {
    int tx = threadIdx.x;            // 0..31
    int ty = threadIdx.y;            // 0..7
    int b  = blockIdx.z;
    int x0 = blockIdx.x * TXV;
    int y0 = blockIdx.y * TY;
    int xc = x0 + 4 * tx;

    __shared__ float hs[TY + KPOOL - 1][TXV];   // 46 x 128

    // Load 46 hsum rows (with vertical halo, zeros outside).
    for (int r = ty; r < TY + KPOOL - 1; r += NW) {
        int yg = y0 + r - KHALF;
        float4 v = make_float4(0.f, 0.f, 0.f, 0.f);
        if (yg >= 0 && yg < H)
            v = *(const float4*)&g_hsum[((size_t)b * H + yg) * W + xc];
        *(float4*)&hs[r][4 * tx] = v;
    }
    __syncthreads();

    int yl0 = 4 * ty;
    // Running vertical sums for the 4 pixels (columns 4tx..4tx+3).
    float vs0 = 0.f, vs1 = 0.f, vs2 = 0.f, vs3 = 0.f;
#pragma unroll
    for (int d = 0; d < KPOOL; ++d) {
        float4 h = *(float4*)&hs[yl0 + d][4 * tx];
        vs0 += h.x; vs1 += h.y; vs2 += h.z; vs3 += h.w;
    }

    float a1 = 0.0f, a2 = 0.0f, a3 = 0.0f;
    const size_t base = (size_t)b * CHW;

#pragma unroll
    for (int i = 0; i < 4; ++i) {
        int y = y0 + yl0 + i;
        size_t idx = base + (size_t)y * W + xc;

        float4 p0 = *(const float4*)(pred + idx);
        float4 p1 = *(const float4*)(pred + idx + HW);
        float4 p2 = *(const float4*)(pred + idx + 2 * HW);
        float4 t0 = *(const float4*)(tgt + idx);
        float4 t1 = *(const float4*)(tgt + idx + HW);
        float4 t2 = *(const float4*)(tgt + idx + 2 * HW);
        float4 q0 = *(const float4*)(src + idx);
        float4 q1 = *(const float4*)(src + idx + HW);
        float4 q2 = *(const float4*)(src + idx + 2 * HW);

        float wmv[4] = {vs0 * (1.0f / 225.0f), vs1 * (1.0f / 225.0f),
                        vs2 * (1.0f / 225.0f), vs3 * (1.0f / 225.0f)};
        float P0[4] = {p0.x, p0.y, p0.z, p0.w};
        float P1[4] = {p1.x, p1.y, p1.z, p1.w};
        float P2[4] = {p2.x, p2.y, p2.z, p2.w};
        float T0[4] = {t0.x, t0.y, t0.z, t0.w};
        float T1[4] = {t1.x, t1.y, t1.z, t1.w};
        float T2[4] = {t2.x, t2.y, t2.z, t2.w};
        float Q0[4] = {q0.x, q0.y, q0.z, q0.w};
        float Q1[4] = {q1.x, q1.y, q1.z, q1.w};
        float Q2[4] = {q2.x, q2.y, q2.z, q2.w};

#pragma unroll
        for (int k = 0; k < 4; ++k) {
            float d0 = P0[k] - T0[k], d1 = P1[k] - T1[k], d2 = P2[k] - T2[k];
            float al1 = fabsf(d0) + fabsf(d1) + fabsf(d2);
            float wm = wmv[k];
            a1 += al1;
            a2 += al1 * (1.0f + 4.0f * wm);

            float st0 = T0[k] - Q0[k], st1 = T1[k] - Q1[k], st2 = T2[k] - Q2[k];
            float sp0 = P0[k] - Q0[k], sp1 = P1[k] - Q1[k], sp2 = P2[k] - Q2[k];
            float stm = sqrtf(st0 * st0 + st1 * st1 + st2 * st2);
            float spm = sqrtf(sp0 * sp0 + sp1 * sp1 + sp2 * sp2);
            float dot = st0 * sp0 + st1 * sp1 + st2 * sp2;
            float align = dot / (fmaxf(stm, EPSV) * fmaxf(spm, EPSV));
            float magl  = fabsf(spm / (stm + EPSV) - 1.0f);
            a3 += wm * (1.0f - align + 0.5f * magl);
        }

        if (i < 3) {   // slide vertical window down by one row
            float4 add = *(float4*)&hs[yl0 + i + KPOOL][4 * tx];
            float4 sub = *(float4*)&hs[yl0 + i][4 * tx];
            vs0 += add.x - sub.x; vs1 += add.y - sub.y;
            vs2 += add.z - sub.z; vs3 += add.w - sub.w;
        }
    }

    // Warp reduce the three partials.
#pragma unroll
    for (int o = 16; o > 0; o >>= 1) {
        a1 += __shfl_down_sync(0xffffffffu, a1, o);
        a2 += __shfl_down_sync(0xffffffffu, a2, o);
        a3 += __shfl_down_sync(0xffffffffu, a3, o);
    }
    __shared__ float red[NW][3];
    if (tx == 0) { red[ty][0] = a1; red[ty][1] = a2; red[ty][2] = a3; }
    __syncthreads();
    if (ty == 0 && tx == 0) {
        float r1 = 0.0f, r2 = 0.0f, r3 = 0.0f;
#pragma unroll
        for (int w = 0; w < NW; ++w) { r1 += red[w][0]; r2 += red[w][1]; r3 += red[w][2]; }
        atomicAdd(&g_acc[0], (double)r1);
        atomicAdd(&g_acc[1], (double)r2);
        atomicAdd(&g_acc[2], (double)r3);
    }
}

__global__ void k_final(float* __restrict__ out) {
    const double N_ALL = (double)B * C * H * W;     // 12,582,912
    const double N_PIX = (double)B * H * W;         // 4,194,304
    double total = g_acc[0] / N_ALL            // LAMBDA_L1 * l1
                 + 3.0 * g_acc[1] / N_ALL      // LAMBDA_WIN_L1 * win_l1
                 + 2.0 * g_acc[2] / N_PIX;     // LAMBDA_WIN_COLOR * TRANSFORM_WEIGHT * color
    out[0] = (float)total;
}

extern "C" void kernel_launch(void* const* d_in, const int* in_sizes, int n_in,
                              void* d_out, int out_size) {
    const float* pred = (const float*)d_in[0];
    const float* tgt  = (const float*)d_in[1];
    const float* src  = (const float*)d_in[2];
    float* out = (float*)d_out;

    k_hsum<<<B * H, 128>>>(src);
    dim3 grid(W / TXV, H / TY, B);
    dim3 blk(32, NW);
    k_main<<<grid, blk>>>(pred, tgt, src);
    k_final<<<1, 1>>>(out);
}

// round 3
// speedup vs baseline: 1.4340x; 1.0821x over previous
#include <cuda_runtime.h>
#include <cuda_fp16.h>
#include <math.h>

#define B 16
#define C 3
#define H 512
#define W 512
#define HW (H*W)
#define CHW (C*H*W)
#define KPOOL 15
#define KHALF 7
#define EPSV 1e-8f

// scalar accumulators: S1 (l1), S2 (win l1), S3 (color)
__device__ double g_acc[3];
// horizontal sliding-sum of detector map, fp16, [B,H,W]
__device__ __half g_hsum[B*H*W];

__device__ __forceinline__ float fsig(float x) {
    return 1.0f / (1.0f + __expf(-x));
}

// One block per image row (128 threads, 4 px/thread).
// Detector map -> block prefix sum -> window = P[x+7] - P[x-8].
__global__ __launch_bounds__(128) void k_hsum(const float* __restrict__ src) {
    int row = blockIdx.x;            // 0 .. B*H-1
    int b = row >> 9;
    int y = row & (H - 1);
    int tid = threadIdx.x;           // 0..127
    int lane = tid & 31;
    int warp = tid >> 5;

    if (row == 0 && tid < 3) g_acc[tid] = 0.0;

    // P[0..7]=0, P[8..519]=inclusive prefix of m, P[520..527]=row total
    __shared__ float P[528];
    __shared__ float wsum[4];

    const float* s = src + (size_t)b * CHW + (size_t)y * W;
    int x4 = tid * 4;
    float4 cr = *(const float4*)(s + x4);
    float4 cg = *(const float4*)(s + HW + x4);
    float4 cb = *(const float4*)(s + 2 * HW + x4);

    float rr[4] = {cr.x, cr.y, cr.z, cr.w};
    float gg[4] = {cg.x, cg.y, cg.z, cg.w};
    float bb[4] = {cb.x, cb.y, cb.z, cb.w};
    float mv[4];
#pragma unroll
    for (int i = 0; i < 4; ++i) {
        float lum = 0.299f * rr[i] + 0.587f * gg[i] + 0.114f * bb[i];
        float mx = fmaxf(rr[i], fmaxf(gg[i], bb[i]));
        float mn = fminf(rr[i], fminf(gg[i], bb[i]));
        // src rescaled to [0,1]: brightness = 0.5*lum+0.5 ; saturation = 0.5*(mx-mn)
        mv[i] = fsig(10.0f * lum - 3.0f) * fsig(3.0f - 10.0f * (mx - mn));
    }

    // Thread-local inclusive prefix of the 4 values.
    float l0 = mv[0];
    float l1 = l0 + mv[1];
    float l2 = l1 + mv[2];
    float l3 = l2 + mv[3];

    // Warp inclusive scan of per-thread totals.
    float v = l3;
#pragma unroll
    for (int o = 1; o < 32; o <<= 1) {
        float n = __shfl_up_sync(0xffffffffu, v, o);
        if (lane >= o) v += n;
    }
    float threadExcl = v - l3;
    if (lane == 31) wsum[warp] = v;
    __syncthreads();

    float w0 = wsum[0], w1 = wsum[1], w2 = wsum[2], w3 = wsum[3];
    float total = w0 + w1 + w2 + w3;
    float blockExcl = (warp > 0 ? w0 : 0.f) + (warp > 1 ? w1 : 0.f) + (warp > 2 ? w2 : 0.f);
    float base = blockExcl + threadExcl;

    *(float4*)&P[8 + x4] = make_float4(base + l0, base + l1, base + l2, base + l3);
    if (tid < 8) { P[tid] = 0.0f; P[520 + tid] = total; }
    __syncthreads();

    // hsum(x) = prefix[x+7] - prefix[x-8] = P[x+15] - P[x] (pads handle edges).
    // Strided mapping -> conflict-free stride-1 LDS, coalesced half stores.
    __half* out = g_hsum + (size_t)row * W;
#pragma unroll
    for (int j = 0; j < 4; ++j) {
        int x = tid + 128 * j;
        out[x] = __float2half(P[x + 15] - P[x]);
    }
}

#define TXV 128      // tile width in pixels
#define TY 32        // tile height
#define NW 8         // warps per block

// Tile kernel: vertical pooling from g_hsum + per-pixel loss math + reduction.
// Each thread owns a 4x4 patch: x = x0+4*tx..+3 (float4), rows y0+4*ty..+3.
__global__ __launch_bounds__(256) void k_main(const float* __restrict__ pred,
                                              const float* __restrict__ tgt,
                                              const float* __restrict__ src) {
    int tx = threadIdx.x;            // 0..31
    int ty = threadIdx.y;            // 0..7
    int b  = blockIdx.z;
    int x0 = blockIdx.x * TXV;
    int y0 = blockIdx.y * TY;
    int xc = x0 + 4 * tx;

    __shared__ float hs[TY + KPOOL - 1][TXV];   // 46 x 128

    // Load 46 hsum rows (with vertical halo, zeros outside), fp16 -> fp32.
    for (int r = ty; r < TY + KPOOL - 1; r += NW) {
        int yg = y0 + r - KHALF;
        float4 v = make_float4(0.f, 0.f, 0.f, 0.f);
        if (yg >= 0 && yg < H) {
            const __half2* hp = (const __half2*)&g_hsum[((size_t)b * H + yg) * W + xc];
            float2 f01 = __half22float2(hp[0]);
            float2 f23 = __half22float2(hp[1]);
            v = make_float4(f01.x, f01.y, f23.x, f23.y);
        }
        *(float4*)&hs[r][4 * tx] = v;
    }
    __syncthreads();

    int yl0 = 4 * ty;
    // Running vertical sums for the 4 pixel columns.
    float vs0 = 0.f, vs1 = 0.f, vs2 = 0.f, vs3 = 0.f;
#pragma unroll
    for (int d = 0; d < KPOOL; ++d) {
        float4 h = *(float4*)&hs[yl0 + d][4 * tx];
        vs0 += h.x; vs1 += h.y; vs2 += h.z; vs3 += h.w;
    }

    float a1 = 0.0f, a2 = 0.0f, a3 = 0.0f;
    const size_t base = (size_t)b * CHW;

#pragma unroll
    for (int i = 0; i < 4; ++i) {
        int y = y0 + yl0 + i;
        size_t idx = base + (size_t)y * W + xc;

        float4 p0 = *(const float4*)(pred + idx);
        float4 p1 = *(const float4*)(pred + idx + HW);
        float4 p2 = *(const float4*)(pred + idx + 2 * HW);
        float4 t0 = *(const float4*)(tgt + idx);
        float4 t1 = *(const float4*)(tgt + idx + HW);
        float4 t2 = *(const float4*)(tgt + idx + 2 * HW);
        float4 q0 = *(const float4*)(src + idx);
        float4 q1 = *(const float4*)(src + idx + HW);
        float4 q2 = *(const float4*)(src + idx + 2 * HW);

        float wmv[4] = {vs0 * (1.0f / 225.0f), vs1 * (1.0f / 225.0f),
                        vs2 * (1.0f / 225.0f), vs3 * (1.0f / 225.0f)};
        float P0[4] = {p0.x, p0.y, p0.z, p0.w};
        float P1[4] = {p1.x, p1.y, p1.z, p1.w};
        float P2[4] = {p2.x, p2.y, p2.z, p2.w};
        float T0[4] = {t0.x, t0.y, t0.z, t0.w};
        float T1[4] = {t1.x, t1.y, t1.z, t1.w};
        float T2[4] = {t2.x, t2.y, t2.z, t2.w};
        float Q0[4] = {q0.x, q0.y, q0.z, q0.w};
        float Q1[4] = {q1.x, q1.y, q1.z, q1.w};
        float Q2[4] = {q2.x, q2.y, q2.z, q2.w};

#pragma unroll
        for (int k = 0; k < 4; ++k) {
            float d0 = P0[k] - T0[k], d1 = P1[k] - T1[k], d2 = P2[k] - T2[k];
            float al1 = fabsf(d0) + fabsf(d1) + fabsf(d2);
            float wm = wmv[k];
            a1 += al1;
            a2 += al1 * (1.0f + 4.0f * wm);

            float st0 = T0[k] - Q0[k], st1 = T1[k] - Q1[k], st2 = T2[k] - Q2[k];
            float sp0 = P0[k] - Q0[k], sp1 = P1[k] - Q1[k], sp2 = P2[k] - Q2[k];
            float stm = sqrtf(st0 * st0 + st1 * st1 + st2 * st2);
            float spm = sqrtf(sp0 * sp0 + sp1 * sp1 + sp2 * sp2);
            float dot = st0 * sp0 + st1 * sp1 + st2 * sp2;
            float align = dot / (fmaxf(stm, EPSV) * fmaxf(spm, EPSV));
            float magl  = fabsf(spm / (stm + EPSV) - 1.0f);
            a3 += wm * (1.0f - align + 0.5f * magl);
        }

        if (i < 3) {   // slide vertical window down one row
            float4 add = *(float4*)&hs[yl0 + i + KPOOL][4 * tx];
            float4 sub = *(float4*)&hs[yl0 + i][4 * tx];
            vs0 += add.x - sub.x; vs1 += add.y - sub.y;
            vs2 += add.z - sub.z; vs3 += add.w - sub.w;
        }
    }

    // Warp reduce the three partials.
#pragma unroll
    for (int o = 16; o > 0; o >>= 1) {
        a1 += __shfl_down_sync(0xffffffffu, a1, o);
        a2 += __shfl_down_sync(0xffffffffu, a2, o);
        a3 += __shfl_down_sync(0xffffffffu, a3, o);
    }
    __shared__ float red[NW][3];
    if (tx == 0) { red[ty][0] = a1; red[ty][1] = a2; red[ty][2] = a3; }
    __syncthreads();
    if (ty == 0 && tx == 0) {
        float r1 = 0.0f, r2 = 0.0f, r3 = 0.0f;
#pragma unroll
        for (int w = 0; w < NW; ++w) { r1 += red[w][0]; r2 += red[w][1]; r3 += red[w][2]; }
        atomicAdd(&g_acc[0], (double)r1);
        atomicAdd(&g_acc[1], (double)r2);
        atomicAdd(&g_acc[2], (double)r3);
    }
}

__global__ void k_final(float* __restrict__ out) {
    const double N_ALL = (double)B * C * H * W;     // 12,582,912
    const double N_PIX = (double)B * H * W;         // 4,194,304
    double total = g_acc[0] / N_ALL            // LAMBDA_L1 * l1
                 + 3.0 * g_acc[1] / N_ALL      // LAMBDA_WIN_L1 * win_l1
                 + 2.0 * g_acc[2] / N_PIX;     // LAMBDA_WIN_COLOR * TRANSFORM_WEIGHT * color
    out[0] = (float)total;
}

extern "C" void kernel_launch(void* const* d_in, const int* in_sizes, int n_in,
                              void* d_out, int out_size) {
    const float* pred = (const float*)d_in[0];
    const float* tgt  = (const float*)d_in[1];
    const float* src  = (const float*)d_in[2];
    float* out = (float*)d_out;

    k_hsum<<<B * H, 128>>>(src);
    dim3 grid(W / TXV, H / TY, B);
    dim3 blk(32, NW);
    k_main<<<grid, blk>>>(pred, tgt, src);
    k_final<<<1, 1>>>(out);
}

// round 4
// speedup vs baseline: 1.5034x; 1.0484x over previous
#include <cuda_runtime.h>
#include <math.h>

#define B 16
#define C 3
#define H 512
#define W 512
#define HW (H*W)
#define CHW (C*H*W)
#define KPOOL 15
#define EPSV 1e-8f

#define TXV 128      // output tile width
#define TY  32       // output tile height
#define NW  8        // warps per block
#define HR  46       // halo rows (TY + 14)
#define MW  160      // m-tile width (TXV + 16 halo cols, padded to 5*32)

// scalar accumulators: S1 (l1), S2 (win l1), S3 (color)
__device__ double g_acc[3];

__device__ __forceinline__ float fast_tanh(float x) {
    float r;
    asm("tanh.approx.f32 %0, %1;" : "=f"(r) : "f"(x));
    return r;
}
// sigmoid(x) = 0.5*tanh(x/2) + 0.5
__device__ __forceinline__ float fsig(float x) {
    return fmaf(0.5f, fast_tanh(0.5f * x), 0.5f);
}

__device__ __forceinline__ float detector(float r, float g, float b) {
    float lum = 0.299f * r + 0.587f * g + 0.114f * b;
    float mx = fmaxf(r, fmaxf(g, b));
    float mn = fminf(r, fminf(g, b));
    // src rescaled to [0,1]: brightness = 0.5*lum+0.5 ; saturation = 0.5*(mx-mn)
    return fsig(10.0f * lum - 3.0f) * fsig(3.0f - 10.0f * (mx - mn));
}

__global__ __launch_bounds__(256) void k_fused(const float* __restrict__ pred,
                                               const float* __restrict__ tgt,
                                               const float* __restrict__ src) {
    const int tx = threadIdx.x;           // 0..31
    const int ty = threadIdx.y;           // 0..7 (warp id)
    const int tid = ty * 32 + tx;
    const int b  = blockIdx.z;
    const int x0 = blockIdx.x * TXV;
    const int y0 = blockIdx.y * TY;
    const int xb = x0 - 8;                // m-tile col 0 == global x xb

    __shared__ float mt[HR][MW];          // detector -> prefix -> hsum (in place)

    const size_t base = (size_t)b * CHW;

    // ---- Phase 1: detector map with halo into smem ----
    // 46 rows x 40 float4-quads; quad is fully in-bounds or fully out (xb % 4 == 0).
#pragma unroll
    for (int i = tid; i < HR * (MW / 4); i += 256) {
        int r = i / (MW / 4);
        int q = i - r * (MW / 4);
        int y = y0 + r - 7;
        int xg = xb + 4 * q;
        float4 m4 = make_float4(0.f, 0.f, 0.f, 0.f);
        if ((unsigned)y < H && (unsigned)xg < W) {
            size_t idx = base + (size_t)y * W + xg;
            float4 cr = *(const float4*)(src + idx);
            float4 cg = *(const float4*)(src + idx + HW);
            float4 cb = *(const float4*)(src + idx + 2 * HW);
            m4.x = detector(cr.x, cg.x, cb.x);
            m4.y = detector(cr.y, cg.y, cb.y);
            m4.z = detector(cr.z, cg.z, cb.z);
            m4.w = detector(cr.w, cg.w, cb.w);
        }
        *(float4*)&mt[r][4 * q] = m4;
    }
    __syncthreads();

    // ---- Phase 2: per-row horizontal pool via in-warp prefix scan ----
    // One warp per row; lane owns m[5*lane .. 5*lane+4].
    for (int r = ty; r < HR; r += NW) {
        int c = 5 * tx;
        float v0 = mt[r][c + 0];
        float v1 = mt[r][c + 1];
        float v2 = mt[r][c + 2];
        float v3 = mt[r][c + 3];
        float v4 = mt[r][c + 4];
        v1 += v0; v2 += v1; v3 += v2; v4 += v3;   // local inclusive prefix
        float s = v4;
#pragma unroll
        for (int o = 1; o < 32; o <<= 1) {
            float n = __shfl_up_sync(0xffffffffu, s, o);
            if (tx >= o) s += n;
        }
        float excl = s - v4;
        // write inclusive prefix P in place
        mt[r][c + 0] = excl + v0;
        mt[r][c + 1] = excl + v1;
        mt[r][c + 2] = excl + v2;
        mt[r][c + 3] = excl + v3;
        mt[r][c + 4] = excl + v4;
        __syncwarp();
        // hsum(x) = P[x+15] - P[x], x = local output col 0..127
        float h0 = mt[r][tx + 15]       - mt[r][tx];
        float h1 = mt[r][tx + 32 + 15]  - mt[r][tx + 32];
        float h2 = mt[r][tx + 64 + 15]  - mt[r][tx + 64];
        float h3 = mt[r][tx + 96 + 15]  - mt[r][tx + 96];
        __syncwarp();
        mt[r][tx]      = h0;    // hsum row now lives at cols 0..127
        mt[r][tx + 32] = h1;
        mt[r][tx + 64] = h2;
        mt[r][tx + 96] = h3;
    }
    __syncthreads();

    // ---- Phase 3: vertical 15-tap running sum + per-pixel loss ----
    // Thread owns 4x4 patch: cols 4*tx..+3, rows y0 + 4*ty..+3.
    int yl0 = 4 * ty;
    int xc = x0 + 4 * tx;

    float vs0 = 0.f, vs1 = 0.f, vs2 = 0.f, vs3 = 0.f;
#pragma unroll
    for (int d = 0; d < KPOOL; ++d) {
        float4 h = *(float4*)&mt[yl0 + d][4 * tx];
        vs0 += h.x; vs1 += h.y; vs2 += h.z; vs3 += h.w;
    }

    float a1 = 0.0f, a2 = 0.0f, a3 = 0.0f;

#pragma unroll
    for (int i = 0; i < 4; ++i) {
        int y = y0 + yl0 + i;
        size_t idx = base + (size_t)y * W + xc;

        float4 p0 = *(const float4*)(pred + idx);
        float4 p1 = *(const float4*)(pred + idx + HW);
        float4 p2 = *(const float4*)(pred + idx + 2 * HW);
        float4 t0 = *(const float4*)(tgt + idx);
        float4 t1 = *(const float4*)(tgt + idx + HW);
        float4 t2 = *(const float4*)(tgt + idx + 2 * HW);
        float4 q0 = *(const float4*)(src + idx);
        float4 q1 = *(const float4*)(src + idx + HW);
        float4 q2 = *(const float4*)(src + idx + 2 * HW);

        float wmv[4] = {vs0 * (1.0f / 225.0f), vs1 * (1.0f / 225.0f),
                        vs2 * (1.0f / 225.0f), vs3 * (1.0f / 225.0f)};
        float P0[4] = {p0.x, p0.y, p0.z, p0.w};
        float P1[4] = {p1.x, p1.y, p1.z, p1.w};
        float P2[4] = {p2.x, p2.y, p2.z, p2.w};
        float T0[4] = {t0.x, t0.y, t0.z, t0.w};
        float T1[4] = {t1.x, t1.y, t1.z, t1.w};
        float T2[4] = {t2.x, t2.y, t2.z, t2.w};
        float Q0[4] = {q0.x, q0.y, q0.z, q0.w};
        float Q1[4] = {q1.x, q1.y, q1.z, q1.w};
        float Q2[4] = {q2.x, q2.y, q2.z, q2.w};

#pragma unroll
        for (int k = 0; k < 4; ++k) {
            float d0 = P0[k] - T0[k], d1 = P1[k] - T1[k], d2 = P2[k] - T2[k];
            float al1 = fabsf(d0) + fabsf(d1) + fabsf(d2);
            float wm = wmv[k];
            a1 += al1;
            a2 += al1 * (1.0f + 4.0f * wm);

            float st0 = T0[k] - Q0[k], st1 = T1[k] - Q1[k], st2 = T2[k] - Q2[k];
            float sp0 = P0[k] - Q0[k], sp1 = P1[k] - Q1[k], sp2 = P2[k] - Q2[k];
            float stm = sqrtf(st0 * st0 + st1 * st1 + st2 * st2);
            float spm = sqrtf(sp0 * sp0 + sp1 * sp1 + sp2 * sp2);
            float dot = st0 * sp0 + st1 * sp1 + st2 * sp2;
            float align = dot / (fmaxf(stm, EPSV) * fmaxf(spm, EPSV));
            float magl  = fabsf(spm / (stm + EPSV) - 1.0f);
            a3 += wm * (1.0f - align + 0.5f * magl);
        }

        if (i < 3) {   // slide vertical window down one row
            float4 add = *(float4*)&mt[yl0 + i + KPOOL][4 * tx];
            float4 sub = *(float4*)&mt[yl0 + i][4 * tx];
            vs0 += add.x - sub.x; vs1 += add.y - sub.y;
            vs2 += add.z - sub.z; vs3 += add.w - sub.w;
        }
    }

    // ---- Reduction ----
#pragma unroll
    for (int o = 16; o > 0; o >>= 1) {
        a1 += __shfl_down_sync(0xffffffffu, a1, o);
        a2 += __shfl_down_sync(0xffffffffu, a2, o);
        a3 += __shfl_down_sync(0xffffffffu, a3, o);
    }
    __shared__ float red[NW][3];
    if (tx == 0) { red[ty][0] = a1; red[ty][1] = a2; red[ty][2] = a3; }
    __syncthreads();
    if (ty == 0 && tx == 0) {
        float r1 = 0.0f, r2 = 0.0f, r3 = 0.0f;
#pragma unroll
        for (int w = 0; w < NW; ++w) { r1 += red[w][0]; r2 += red[w][1]; r3 += red[w][2]; }
        atomicAdd(&g_acc[0], (double)r1);
        atomicAdd(&g_acc[1], (double)r2);
        atomicAdd(&g_acc[2], (double)r3);
    }
}

// Combine + reset accumulators (so each graph replay starts from zero;
// initial state at module load is also zero).
__global__ void k_final(float* __restrict__ out) {
    const double N_ALL = (double)B * C * H * W;
    const double N_PIX = (double)B * H * W;
    double total = g_acc[0] / N_ALL            // LAMBDA_L1 * l1
                 + 3.0 * g_acc[1] / N_ALL      // LAMBDA_WIN_L1 * win_l1
                 + 2.0 * g_acc[2] / N_PIX;     // LAMBDA_WIN_COLOR * TRANSFORM_WEIGHT * color
    out[0] = (float)total;
    g_acc[0] = 0.0; g_acc[1] = 0.0; g_acc[2] = 0.0;
}

extern "C" void kernel_launch(void* const* d_in, const int* in_sizes, int n_in,
                              void* d_out, int out_size) {
    const float* pred = (const float*)d_in[0];
    const float* tgt  = (const float*)d_in[1];
    const float* src  = (const float*)d_in[2];
    float* out = (float*)d_out;

    dim3 grid(W / TXV, H / TY, B);
    dim3 blk(32, NW);
    k_fused<<<grid, blk>>>(pred, tgt, src);
    k_final<<<1, 1>>>(out);
}

// round 5
// speedup vs baseline: 1.5720x; 1.0457x over previous
#include <cuda_runtime.h>
#include <math.h>

#define B 16
#define C 3
#define H 512
#define W 512
#define HW (H*W)
#define CHW (C*H*W)
#define KPOOL 15

#define TXV 128      // output tile width
#define TY  32       // output tile height
#define NW  8        // warps per block
#define HR  46       // halo rows (TY + 14)
#define MW  160      // m-tile width (TXV + 16 halo cols = 5*32)
#define NBLOCKS ((W/TXV)*(H/TY)*B)   // 1024

// scalar accumulators: S1 (l1), S2w (al1*wm), S3 (color)
__device__ double g_acc[3];
__device__ unsigned g_ticket;

__device__ __forceinline__ float fast_tanh(float x) {
    float r;
    asm("tanh.approx.f32 %0, %1;" : "=f"(r) : "f"(x));
    return r;
}
// sigmoid(x) = 0.5*tanh(x/2) + 0.5
__device__ __forceinline__ float fsig(float x) {
    return fmaf(0.5f, fast_tanh(0.5f * x), 0.5f);
}

__device__ __forceinline__ float detector(float r, float g, float b) {
    float lum = 0.299f * r + 0.587f * g + 0.114f * b;
    float mx = fmaxf(r, fmaxf(g, b));
    float mn = fminf(r, fminf(g, b));
    // src rescaled to [0,1]: brightness = 0.5*lum+0.5 ; saturation = 0.5*(mx-mn)
    return fsig(10.0f * lum - 3.0f) * fsig(3.0f - 10.0f * (mx - mn));
}

__global__ __launch_bounds__(256) void k_fused(const float* __restrict__ pred,
                                               const float* __restrict__ tgt,
                                               const float* __restrict__ src,
                                               float* __restrict__ out) {
    const int tx = threadIdx.x;           // 0..31
    const int ty = threadIdx.y;           // 0..7 (warp id)
    const int tid = ty * 32 + tx;
    const int b  = blockIdx.z;
    const int x0 = blockIdx.x * TXV;
    const int y0 = blockIdx.y * TY;
    const int xb = x0 - 8;                // m-tile col 0 == global x xb

    __shared__ float mt[HR][MW];          // detector -> prefix -> hsum (in place)

    const size_t base = (size_t)b * CHW;

    // ---- Phase 1: detector map with halo into smem ----
#pragma unroll
    for (int i = tid; i < HR * (MW / 4); i += 256) {
        int r = i / (MW / 4);
        int q = i - r * (MW / 4);
        int y = y0 + r - 7;
        int xg = xb + 4 * q;
        float4 m4 = make_float4(0.f, 0.f, 0.f, 0.f);
        if ((unsigned)y < H && (unsigned)xg < W) {
            size_t idx = base + (size_t)y * W + xg;
            float4 cr = *(const float4*)(src + idx);
            float4 cg = *(const float4*)(src + idx + HW);
            float4 cb = *(const float4*)(src + idx + 2 * HW);
            m4.x = detector(cr.x, cg.x, cb.x);
            m4.y = detector(cr.y, cg.y, cb.y);
            m4.z = detector(cr.z, cg.z, cb.z);
            m4.w = detector(cr.w, cg.w, cb.w);
        }
        *(float4*)&mt[r][4 * q] = m4;
    }
    __syncthreads();

    // ---- Phase 2: per-row horizontal pool via in-warp prefix scan ----
    for (int r = ty; r < HR; r += NW) {
        int c = 5 * tx;
        float v0 = mt[r][c + 0];
        float v1 = mt[r][c + 1];
        float v2 = mt[r][c + 2];
        float v3 = mt[r][c + 3];
        float v4 = mt[r][c + 4];
        v1 += v0; v2 += v1; v3 += v2; v4 += v3;   // local inclusive prefix
        float s = v4;
#pragma unroll
        for (int o = 1; o < 32; o <<= 1) {
            float n = __shfl_up_sync(0xffffffffu, s, o);
            if (tx >= o) s += n;
        }
        float excl = s - v4;
        mt[r][c + 0] = excl + v0;
        mt[r][c + 1] = excl + v1;
        mt[r][c + 2] = excl + v2;
        mt[r][c + 3] = excl + v3;
        mt[r][c + 4] = excl + v4;
        __syncwarp();
        float h0 = mt[r][tx + 15]       - mt[r][tx];
        float h1 = mt[r][tx + 32 + 15]  - mt[r][tx + 32];
        float h2 = mt[r][tx + 64 + 15]  - mt[r][tx + 64];
        float h3 = mt[r][tx + 96 + 15]  - mt[r][tx + 96];
        __syncwarp();
        mt[r][tx]      = h0;    // hsum row now lives at cols 0..127
        mt[r][tx + 32] = h1;
        mt[r][tx + 64] = h2;
        mt[r][tx + 96] = h3;
    }
    __syncthreads();

    // ---- Phase 3: vertical 15-tap running sum + per-pixel loss ----
    int yl0 = 4 * ty;
    int xc = x0 + 4 * tx;

    float vs0 = 0.f, vs1 = 0.f, vs2 = 0.f, vs3 = 0.f;
#pragma unroll
    for (int d = 0; d < KPOOL; ++d) {
        float4 h = *(float4*)&mt[yl0 + d][4 * tx];
        vs0 += h.x; vs1 += h.y; vs2 += h.z; vs3 += h.w;
    }

    float a1 = 0.0f, a2 = 0.0f, a3 = 0.0f;   // S1, sum(al1*wm), color

#pragma unroll
    for (int i = 0; i < 4; ++i) {
        int y = y0 + yl0 + i;
        size_t idx = base + (size_t)y * W + xc;

        float4 p0 = *(const float4*)(pred + idx);
        float4 p1 = *(const float4*)(pred + idx + HW);
        float4 p2 = *(const float4*)(pred + idx + 2 * HW);
        float4 t0 = *(const float4*)(tgt + idx);
        float4 t1 = *(const float4*)(tgt + idx + HW);
        float4 t2 = *(const float4*)(tgt + idx + 2 * HW);
        float4 q0 = *(const float4*)(src + idx);
        float4 q1 = *(const float4*)(src + idx + HW);
        float4 q2 = *(const float4*)(src + idx + 2 * HW);

        float wmv[4] = {vs0 * (1.0f / 225.0f), vs1 * (1.0f / 225.0f),
                        vs2 * (1.0f / 225.0f), vs3 * (1.0f / 225.0f)};
        float P0[4] = {p0.x, p0.y, p0.z, p0.w};
        float P1[4] = {p1.x, p1.y, p1.z, p1.w};
        float P2[4] = {p2.x, p2.y, p2.z, p2.w};
        float T0[4] = {t0.x, t0.y, t0.z, t0.w};
        float T1[4] = {t1.x, t1.y, t1.z, t1.w};
        float T2[4] = {t2.x, t2.y, t2.z, t2.w};
        float Q0[4] = {q0.x, q0.y, q0.z, q0.w};
        float Q1[4] = {q1.x, q1.y, q1.z, q1.w};
        float Q2[4] = {q2.x, q2.y, q2.z, q2.w};

#pragma unroll
        for (int k = 0; k < 4; ++k) {
            float d0 = P0[k] - T0[k], d1 = P1[k] - T1[k], d2 = P2[k] - T2[k];
            float al1 = fabsf(d0) + fabsf(d1) + fabsf(d2);
            float wm = wmv[k];
            a1 += al1;
            a2 += al1 * wm;

            float st0 = T0[k] - Q0[k], st1 = T1[k] - Q1[k], st2 = T2[k] - Q2[k];
            float sp0 = P0[k] - Q0[k], sp1 = P1[k] - Q1[k], sp2 = P2[k] - Q2[k];
            float stm2 = fmaxf(st0 * st0 + st1 * st1 + st2 * st2, 1e-24f);
            float spm2 = fmaxf(sp0 * sp0 + sp1 * sp1 + sp2 * sp2, 1e-24f);
            float dot  = st0 * sp0 + st1 * sp1 + st2 * sp2;
            float istm = rsqrtf(stm2);
            float ispm = rsqrtf(spm2);
            float ii = istm * ispm;
            float align = dot * ii;
            float magl  = fabsf(spm2 * ii - 1.0f);   // spm/stm = spm2*ispm*istm
            a3 += wm * (1.0f - align + 0.5f * magl);
        }

        if (i < 3) {   // slide vertical window down one row
            float4 add = *(float4*)&mt[yl0 + i + KPOOL][4 * tx];
            float4 sub = *(float4*)&mt[yl0 + i][4 * tx];
            vs0 += add.x - sub.x; vs1 += add.y - sub.y;
            vs2 += add.z - sub.z; vs3 += add.w - sub.w;
        }
    }

    // ---- Reduction ----
#pragma unroll
    for (int o = 16; o > 0; o >>= 1) {
        a1 += __shfl_down_sync(0xffffffffu, a1, o);
        a2 += __shfl_down_sync(0xffffffffu, a2, o);
        a3 += __shfl_down_sync(0xffffffffu, a3, o);
    }
    __shared__ float red[NW][3];
    __shared__ bool amLast;
    if (tx == 0) { red[ty][0] = a1; red[ty][1] = a2; red[ty][2] = a3; }
    __syncthreads();
    if (ty == 0 && tx == 0) {
        float r1 = 0.0f, r2 = 0.0f, r3 = 0.0f;
#pragma unroll
        for (int w = 0; w < NW; ++w) { r1 += red[w][0]; r2 += red[w][1]; r3 += red[w][2]; }
        atomicAdd(&g_acc[0], (double)r1);
        atomicAdd(&g_acc[1], (double)r2);
        atomicAdd(&g_acc[2], (double)r3);
        __threadfence();
        unsigned t = atomicAdd(&g_ticket, 1u);
        amLast = (t == NBLOCKS - 1);
    }
    __syncthreads();

    // ---- Last block folds the final combine (no extra kernel launch) ----
    if (amLast && ty == 0 && tx == 0) {
        const double N_ALL = (double)B * C * H * W;
        const double N_PIX = (double)B * H * W;
        double S1 = g_acc[0], S2w = g_acc[1], S3 = g_acc[2];
        // l1 + 3*win_l1 + 2*color ; win_l1 = (S1 + 4*S2w)/N_ALL
        double total = 4.0 * S1 / N_ALL + 12.0 * S2w / N_ALL + 2.0 * S3 / N_PIX;
        out[0] = (float)total;
        // reset for next graph replay
        g_acc[0] = 0.0; g_acc[1] = 0.0; g_acc[2] = 0.0;
        g_ticket = 0u;
    }
}

extern "C" void kernel_launch(void* const* d_in, const int* in_sizes, int n_in,
                              void* d_out, int out_size) {
    const float* pred = (const float*)d_in[0];
    const float* tgt  = (const float*)d_in[1];
    const float* src  = (const float*)d_in[2];
    float* out = (float*)d_out;

    dim3 grid(W / TXV, H / TY, B);
    dim3 blk(32, NW);
    k_fused<<<grid, blk>>>(pred, tgt, src, out);
}